// round 1
// baseline (speedup 1.0000x reference)
#include <cuda_runtime.h>
#include <cuda_bf16.h>
#include <math.h>
#include <stdint.h>

// ---------------------------------------------------------------------------
// KAN layer as one concatenated GEMM:
//   out[b,o] = sum_i w[i,o]*silu(x[b,i]) + sum_{i,k} bx[b,i,k]*(w[i,o]*c[i,o,k])
// K-axis layout (KTOT = 7168):
//   [0    ,  512): A = bf16_hi(silu(x)) , B = bf16_hi(w)
//   [512  , 1024): A = bf16_lo(silu(x)) , B = bf16_hi(w)
//   [1024 , 1536): A = bf16_hi(silu(x)) , B = bf16_lo(w)
//   [1536 , 7168): A = bf16(bx[b,i,kk]) , B = bf16(w[i,o]*c[i,o,kk]), k=1536+i*11+kk
// ---------------------------------------------------------------------------

#define BATCH 1024
#define NIN   512
#define NOUT  512
#define NB    11
#define KSIL  1536
#define KTOT  7168          // 1536 + 512*11, divisible by 64

#define BM 128
#define BN 64
#define BK 64
#define NKT (KTOT / BK)     // 112
#define ASTAGE (BM * BK * 2)  // 16384 B
#define BSTAGE (BN * BK * 2)  // 8192 B

// Scratch (allocation-free rule: __device__ globals)
__device__ __align__(128) __nv_bfloat16 g_A [(size_t)BATCH * KTOT];  // (1024, 7168)
__device__ __align__(128) __nv_bfloat16 g_Bt[(size_t)NOUT  * KTOT];  // (512 , 7168)  Bt[o][k]

// ---------------------------------------------------------------------------
// Prep A: silu hi/lo split + cubic B-spline basis (Cox-de Boor, fp32)
// knots: t_m = -5.25 + 0.75*m, m = 0..14 (exact in fp32)
// ---------------------------------------------------------------------------
__global__ void __launch_bounds__(256) prep_a_kernel(const float* __restrict__ X) {
    int idx = blockIdx.x * blockDim.x + threadIdx.x;
    if (idx >= BATCH * NIN) return;
    int b = idx >> 9;
    int i = idx & 511;
    float x = X[idx];

    float s = x / (1.0f + expf(-x));   // silu, fp32
    __nv_bfloat16 shi = __float2bfloat16(s);
    float shif = __bfloat162float(shi);
    __nv_bfloat16 slo = __float2bfloat16(s - shif);

    __nv_bfloat16* row = g_A + (size_t)b * KTOT;
    row[i]        = shi;
    row[512 + i]  = slo;
    row[1024 + i] = shi;

    // degree-0 basis over 14 intervals
    float Bv[14];
#pragma unroll
    for (int m = 0; m < 14; m++) {
        float tl = -5.25f + 0.75f * m;
        float tr = tl + 0.75f;
        Bv[m] = (x >= tl && x < tr) ? 1.0f : 0.0f;
    }
    // Cox-de Boor up to degree 3 (uniform knots: denominators = d*h)
#pragma unroll
    for (int d = 1; d <= 3; d++) {
        float inv = 1.0f / (0.75f * (float)d);
#pragma unroll
        for (int m = 0; m < 14 - 3; m++) {  // upper bound 11 suffices for all d<=3 outputs we keep
            // we still need Bv[m+1] valid at each level for m < 14-d; compute full range:
            ;
        }
#pragma unroll
        for (int m = 0; m < 13; m++) {
            if (m < 14 - d) {
                float tm    = -5.25f + 0.75f * m;
                float left  = (x - tm) * inv;
                float right = ((tm + 0.75f * (float)(d + 1)) - x) * inv;
                Bv[m] = left * Bv[m] + right * Bv[m + 1];
            }
        }
    }
#pragma unroll
    for (int kk = 0; kk < NB; kk++)
        row[KSIL + i * NB + kk] = __float2bfloat16(Bv[kk]);
}

// ---------------------------------------------------------------------------
// Prep B: Bt[o][k] weight matrix (w hi/lo + fused w*c spline coefficients)
// ---------------------------------------------------------------------------
__global__ void __launch_bounds__(256) prep_b_kernel(const float* __restrict__ W,
                                                     const float* __restrict__ C) {
    int idx = blockIdx.x * blockDim.x + threadIdx.x;
    if (idx >= NIN * NOUT) return;
    int o = idx >> 9;
    int i = idx & 511;

    float wv = W[i * NOUT + o];
    __nv_bfloat16 whi = __float2bfloat16(wv);
    float whif = __bfloat162float(whi);
    __nv_bfloat16 wlo = __float2bfloat16(wv - whif);

    __nv_bfloat16* row = g_Bt + (size_t)o * KTOT;
    row[i]        = whi;
    row[512 + i]  = whi;
    row[1024 + i] = wlo;

    const float* crow = C + ((size_t)i * NOUT + o) * NB;
#pragma unroll
    for (int kk = 0; kk < NB; kk++)
        row[KSIL + i * NB + kk] = __float2bfloat16(wv * crow[kk]);
}

// ---------------------------------------------------------------------------
// GEMM: C(1024x512, f32) = A(1024x7168, bf16) x Bt(512x7168, bf16)^T
// mma.sync m16n8k16 bf16, cp.async double-buffered, XOR-swizzled smem
// ---------------------------------------------------------------------------
__device__ __forceinline__ void cpa16(uint32_t dst, const void* src) {
    asm volatile("cp.async.cg.shared.global [%0], [%1], 16;\n" :: "r"(dst), "l"(src));
}

#define LDSM_X4(r, addr)                                                       \
    asm volatile("ldmatrix.sync.aligned.m8n8.x4.shared.b16 {%0,%1,%2,%3}, [%4];\n" \
                 : "=r"((r)[0]), "=r"((r)[1]), "=r"((r)[2]), "=r"((r)[3])      \
                 : "r"(addr))

#define MMA16816(d, a, b0, b1)                                                 \
    asm volatile("mma.sync.aligned.m16n8k16.row.col.f32.bf16.bf16.f32 "        \
                 "{%0,%1,%2,%3}, {%4,%5,%6,%7}, {%8,%9}, {%0,%1,%2,%3};\n"     \
                 : "+f"((d)[0]), "+f"((d)[1]), "+f"((d)[2]), "+f"((d)[3])      \
                 : "r"((a)[0]), "r"((a)[1]), "r"((a)[2]), "r"((a)[3]),         \
                   "r"(b0), "r"(b1))

__device__ __forceinline__ void load_tiles(int m0, int n0, int kt, int s, int tid,
                                           uint32_t sA_base, uint32_t sB_base) {
    const char* Ag = (const char*)(g_A + (size_t)m0 * KTOT + kt * BK);
#pragma unroll
    for (int it = 0; it < 4; it++) {
        int t = tid + it * 256;
        int r = t >> 3, c = t & 7;
        uint32_t dst = sA_base + s * ASTAGE + r * (BK * 2) + (((c ^ (r & 7))) << 4);
        cpa16(dst, Ag + (size_t)r * (KTOT * 2) + (c << 4));
    }
    const char* Bg = (const char*)(g_Bt + (size_t)n0 * KTOT + kt * BK);
#pragma unroll
    for (int it = 0; it < 2; it++) {
        int t = tid + it * 256;
        int r = t >> 3, c = t & 7;
        uint32_t dst = sB_base + s * BSTAGE + r * (BK * 2) + (((c ^ (r & 7))) << 4);
        cpa16(dst, Bg + (size_t)r * (KTOT * 2) + (c << 4));
    }
    asm volatile("cp.async.commit_group;\n" ::);
}

__global__ void __launch_bounds__(256, 1) kan_gemm_kernel(float* __restrict__ Out) {
    __shared__ __align__(1024) __nv_bfloat16 sA[2][BM][BK];  // 32 KB
    __shared__ __align__(1024) __nv_bfloat16 sB[2][BN][BK];  // 16 KB

    const int tid  = threadIdx.x;
    const int m0   = blockIdx.x * BM;
    const int n0   = blockIdx.y * BN;
    const uint32_t sA_base = (uint32_t)__cvta_generic_to_shared(&sA[0][0][0]);
    const uint32_t sB_base = (uint32_t)__cvta_generic_to_shared(&sB[0][0][0]);

    const int lane = tid & 31;
    const int warp = tid >> 5;
    const int wm   = warp >> 1;   // 0..3  (m-position, 32 rows each)
    const int wn   = warp & 1;    // 0..1  (n-position, 32 cols each)
    const int lr   = lane & 15;
    const int hf   = lane >> 4;

    float acc[2][4][4];
#pragma unroll
    for (int mt = 0; mt < 2; mt++)
#pragma unroll
        for (int nt = 0; nt < 4; nt++)
#pragma unroll
            for (int e = 0; e < 4; e++) acc[mt][nt][e] = 0.0f;

    load_tiles(m0, n0, 0, 0, tid, sA_base, sB_base);

    for (int kt = 0; kt < NKT; kt++) {
        const int cur = kt & 1;
        if (kt + 1 < NKT) {
            load_tiles(m0, n0, kt + 1, (kt + 1) & 1, tid, sA_base, sB_base);
            asm volatile("cp.async.wait_group 1;\n" ::);
        } else {
            asm volatile("cp.async.wait_group 0;\n" ::);
        }
        __syncthreads();

#pragma unroll
        for (int ks = 0; ks < 4; ks++) {
            uint32_t af[2][4], bf[2][4];
#pragma unroll
            for (int mt = 0; mt < 2; mt++) {
                int r  = wm * 32 + mt * 16 + lr;
                int ch = (ks * 2 + hf) ^ (r & 7);
                uint32_t addr = sA_base + cur * ASTAGE + r * (BK * 2) + (ch << 4);
                LDSM_X4(af[mt], addr);
            }
#pragma unroll
            for (int p = 0; p < 2; p++) {
                int r  = wn * 32 + p * 16 + lr;
                int ch = (ks * 2 + hf) ^ (r & 7);
                uint32_t addr = sB_base + cur * BSTAGE + r * (BK * 2) + (ch << 4);
                LDSM_X4(bf[p], addr);
            }
#pragma unroll
            for (int mt = 0; mt < 2; mt++)
#pragma unroll
                for (int nt = 0; nt < 4; nt++) {
                    int p = nt >> 1, q = nt & 1;
                    MMA16816(acc[mt][nt], af[mt], bf[p][q], bf[p][q + 2]);
                }
        }
        __syncthreads();
    }

    // epilogue: f32 direct to gmem
#pragma unroll
    for (int mt = 0; mt < 2; mt++)
#pragma unroll
        for (int nt = 0; nt < 4; nt++) {
            int row0 = m0 + wm * 32 + mt * 16 + (lane >> 2);
            int col  = n0 + wn * 32 + nt * 8 + (lane & 3) * 2;
            *(float2*)&Out[(size_t)row0 * NOUT + col] =
                make_float2(acc[mt][nt][0], acc[mt][nt][1]);
            *(float2*)&Out[(size_t)(row0 + 8) * NOUT + col] =
                make_float2(acc[mt][nt][2], acc[mt][nt][3]);
        }
}

// ---------------------------------------------------------------------------
extern "C" void kernel_launch(void* const* d_in, const int* in_sizes, int n_in,
                              void* d_out, int out_size) {
    // identify inputs by element count (all distinct): x=524288, c=2883584, w=262144
    const float* X = nullptr;
    const float* C = nullptr;
    const float* W = nullptr;
    for (int i = 0; i < n_in; i++) {
        if      (in_sizes[i] == BATCH * NIN)      X = (const float*)d_in[i];
        else if (in_sizes[i] == NIN * NOUT * NB)  C = (const float*)d_in[i];
        else if (in_sizes[i] == NIN * NOUT)       W = (const float*)d_in[i];
    }

    prep_a_kernel<<<(BATCH * NIN) / 256, 256>>>(X);
    prep_b_kernel<<<(NIN * NOUT) / 256, 256>>>(W, C);

    dim3 grid(BATCH / BM, NOUT / BN);   // (8, 8) = 64 CTAs
    kan_gemm_kernel<<<grid, 256>>>((float*)d_out);
}

// round 2
// speedup vs baseline: 2.0409x; 2.0409x over previous
#include <cuda_runtime.h>
#include <cuda_bf16.h>
#include <math.h>
#include <stdint.h>

// ---------------------------------------------------------------------------
// KAN layer as one concatenated GEMM:
//   out[b,o] = sum_i w[i,o]*silu(x[b,i]) + sum_{i,k} bx[b,i,k]*(w[i,o]*c[i,o,k])
// K-axis layout (KTOT = 7168), spline region now COLUMN-BLOCKED for coalescing:
//   [0    ,  512): A = bf16_hi(silu(x)) , B = bf16_hi(w)
//   [512  , 1024): A = bf16_lo(silu(x)) , B = bf16_hi(w)
//   [1024 , 1536): A = bf16_hi(silu(x)) , B = bf16_lo(w)
//   [1536 , 7168): k = 1536 + kk*512 + i :
//                  A = bf16(bx[b,i,kk]) , B = bf16(w[i,o]*c[i,o,kk])
// ---------------------------------------------------------------------------

#define BATCH 1024
#define NIN   512
#define NOUT  512
#define NB    11
#define KSIL  1536
#define KTOT  7168

#define BM 128
#define BN 128
#define BK 128
#define SPLITK 4
#define KSPLIT (KTOT / SPLITK)     // 1792
#define ITERS  (KSPLIT / BK)       // 14
#define STAGES 3

#define ASTAGE (BM * BK * 2)       // 32768 B
#define BSTAGE (BN * BK * 2)       // 32768 B
#define SMEM_TOTAL (STAGES * (ASTAGE + BSTAGE))   // 196608 B

// Scratch (allocation-free rule: __device__ globals)
__device__ __align__(128) __nv_bfloat16 g_A [(size_t)BATCH * KTOT];      // 14.7 MB
__device__ __align__(128) __nv_bfloat16 g_Bt[(size_t)NOUT  * KTOT];      // 7.3 MB
__device__ __align__(128) float         g_P [(size_t)SPLITK * BATCH * NOUT]; // 8 MB

// ---------------------------------------------------------------------------
// Cubic B-spline basis (Cox-de Boor). knots t_m = -5.25 + 0.75*m (exact fp32)
// ---------------------------------------------------------------------------
__device__ __forceinline__ void basis11(float x, float* Bv /*[14]*/) {
#pragma unroll
    for (int m = 0; m < 14; m++) {
        float tl = -5.25f + 0.75f * (float)m;
        Bv[m] = (x >= tl && x < tl + 0.75f) ? 1.0f : 0.0f;
    }
#pragma unroll
    for (int d = 1; d <= 3; d++) {
        float inv = 1.0f / (0.75f * (float)d);
#pragma unroll
        for (int m = 0; m < 13; m++) {
            if (m < 14 - d) {
                float tm    = -5.25f + 0.75f * (float)m;
                float left  = (x - tm) * inv;
                float right = ((tm + 0.75f * (float)(d + 1)) - x) * inv;
                Bv[m] = left * Bv[m] + right * Bv[m + 1];
            }
        }
    }
}

// ---------------------------------------------------------------------------
// Prep A: one thread handles 2 consecutive i of one batch row -> bf16x2 stores
// ---------------------------------------------------------------------------
__global__ void __launch_bounds__(256) prep_a_kernel(const float* __restrict__ X) {
    int pid = blockIdx.x * 256 + threadIdx.x;           // 262144 pairs
    int b  = pid >> 8;
    int ip = (pid & 255) << 1;

    float2 xv = *(const float2*)(X + (size_t)b * NIN + ip);

    float s0 = xv.x / (1.0f + expf(-xv.x));
    float s1 = xv.y / (1.0f + expf(-xv.y));
    __nv_bfloat16 shi0 = __float2bfloat16(s0), shi1 = __float2bfloat16(s1);
    __nv_bfloat16 slo0 = __float2bfloat16(s0 - __bfloat162float(shi0));
    __nv_bfloat16 slo1 = __float2bfloat16(s1 - __bfloat162float(shi1));

    __nv_bfloat16* row = g_A + (size_t)b * KTOT;
    *(__nv_bfloat162*)(row + ip)        = __nv_bfloat162(shi0, shi1);
    *(__nv_bfloat162*)(row + 512 + ip)  = __nv_bfloat162(slo0, slo1);
    *(__nv_bfloat162*)(row + 1024 + ip) = __nv_bfloat162(shi0, shi1);

    float B0[14], B1[14];
    basis11(xv.x, B0);
    basis11(xv.y, B1);
#pragma unroll
    for (int kk = 0; kk < NB; kk++)
        *(__nv_bfloat162*)(row + KSIL + kk * NIN + ip) =
            __nv_bfloat162(__float2bfloat16(B0[kk]), __float2bfloat16(B1[kk]));
}

// ---------------------------------------------------------------------------
// Prep B: one thread handles 2 consecutive i for one o -> coalesced bf16x2
// ---------------------------------------------------------------------------
__global__ void __launch_bounds__(256) prep_b_kernel(const float* __restrict__ W,
                                                     const float* __restrict__ C) {
    int pid = blockIdx.x * 256 + threadIdx.x;           // 131072 pairs
    int o  = pid >> 8;
    int ip = (pid & 255) << 1;

    float w0 = W[(size_t)ip * NOUT + o];
    float w1 = W[(size_t)(ip + 1) * NOUT + o];
    __nv_bfloat16 whi0 = __float2bfloat16(w0), whi1 = __float2bfloat16(w1);
    __nv_bfloat16 wlo0 = __float2bfloat16(w0 - __bfloat162float(whi0));
    __nv_bfloat16 wlo1 = __float2bfloat16(w1 - __bfloat162float(whi1));

    __nv_bfloat16* row = g_Bt + (size_t)o * KTOT;
    *(__nv_bfloat162*)(row + ip)        = __nv_bfloat162(whi0, whi1);
    *(__nv_bfloat162*)(row + 512 + ip)  = __nv_bfloat162(whi0, whi1);
    *(__nv_bfloat162*)(row + 1024 + ip) = __nv_bfloat162(wlo0, wlo1);

    const float* c0 = C + ((size_t)ip * NOUT + o) * NB;
    const float* c1 = C + ((size_t)(ip + 1) * NOUT + o) * NB;
#pragma unroll
    for (int kk = 0; kk < NB; kk++)
        *(__nv_bfloat162*)(row + KSIL + kk * NIN + ip) =
            __nv_bfloat162(__float2bfloat16(w0 * c0[kk]),
                           __float2bfloat16(w1 * c1[kk]));
}

// ---------------------------------------------------------------------------
// GEMM: P[z] += A(1024x7168) x Bt(512x7168)^T over k in [z*1792,(z+1)*1792)
// mma.sync m16n8k16 bf16, 3-stage cp.async, XOR-swizzled smem
// smem per stage: two 64-col sub-tiles per operand, each row = 128B swizzled
// ---------------------------------------------------------------------------
__device__ __forceinline__ void cpa16(uint32_t dst, const void* src) {
    asm volatile("cp.async.cg.shared.global [%0], [%1], 16;\n" :: "r"(dst), "l"(src));
}

#define LDSM_X4(r, addr)                                                       \
    asm volatile("ldmatrix.sync.aligned.m8n8.x4.shared.b16 {%0,%1,%2,%3}, [%4];\n" \
                 : "=r"((r)[0]), "=r"((r)[1]), "=r"((r)[2]), "=r"((r)[3])      \
                 : "r"(addr))

#define MMA16816(d, a, b0, b1)                                                 \
    asm volatile("mma.sync.aligned.m16n8k16.row.col.f32.bf16.bf16.f32 "        \
                 "{%0,%1,%2,%3}, {%4,%5,%6,%7}, {%8,%9}, {%0,%1,%2,%3};\n"     \
                 : "+f"((d)[0]), "+f"((d)[1]), "+f"((d)[2]), "+f"((d)[3])      \
                 : "r"((a)[0]), "r"((a)[1]), "r"((a)[2]), "r"((a)[3]),         \
                   "r"(b0), "r"(b1))

// sub-tile: 128 rows x 64 cols bf16 = rows of 128B; swizzle chunk c^(r&7)
#define SUBTILE 16384

__device__ __forceinline__ void load_tiles(const char* Ag, const char* Bg,
                                           int kt, int tid,
                                           uint32_t sA, uint32_t sB) {
    int s = kt % STAGES;
    const char* Ak = Ag + (size_t)kt * (BK * 2);
#pragma unroll
    for (int it = 0; it < 8; it++) {
        int t = tid + it * 256;          // 2048 chunks of 16B
        int r = t >> 4, c = t & 15;
        int sub = c >> 3, cc = c & 7;
        uint32_t dst = sA + s * ASTAGE + sub * SUBTILE + r * 128 + ((cc ^ (r & 7)) << 4);
        cpa16(dst, Ak + (size_t)r * (KTOT * 2) + (c << 4));
    }
    const char* Bk = Bg + (size_t)kt * (BK * 2);
#pragma unroll
    for (int it = 0; it < 8; it++) {
        int t = tid + it * 256;
        int r = t >> 4, c = t & 15;
        int sub = c >> 3, cc = c & 7;
        uint32_t dst = sB + s * BSTAGE + sub * SUBTILE + r * 128 + ((cc ^ (r & 7)) << 4);
        cpa16(dst, Bk + (size_t)r * (KTOT * 2) + (c << 4));
    }
    asm volatile("cp.async.commit_group;\n" ::);
}

__global__ void __launch_bounds__(256, 1) kan_gemm_kernel() {
    extern __shared__ __align__(1024) char smem[];
    const uint32_t sA = (uint32_t)__cvta_generic_to_shared(smem);
    const uint32_t sB = sA + STAGES * ASTAGE;

    const int tid  = threadIdx.x;
    const int m0   = blockIdx.x * BM;
    const int n0   = blockIdx.y * BN;
    const int z    = blockIdx.z;

    const char* Ag = (const char*)g_A  + ((size_t)m0 * KTOT + (size_t)z * KSPLIT) * 2;
    const char* Bg = (const char*)g_Bt + ((size_t)n0 * KTOT + (size_t)z * KSPLIT) * 2;

    const int lane = tid & 31;
    const int warp = tid >> 5;
    const int wm   = warp >> 1;   // 0..3 : 32-row band
    const int wn   = warp & 1;    // 0..1 : 64-col band
    const int lr   = lane & 15;
    const int hf   = lane >> 4;

    float acc[2][8][4];
#pragma unroll
    for (int mt = 0; mt < 2; mt++)
#pragma unroll
        for (int nt = 0; nt < 8; nt++)
#pragma unroll
            for (int e = 0; e < 4; e++) acc[mt][nt][e] = 0.0f;

    load_tiles(Ag, Bg, 0, tid, sA, sB);
    load_tiles(Ag, Bg, 1, tid, sA, sB);
    load_tiles(Ag, Bg, 2, tid, sA, sB);

    for (int kt = 0; kt < ITERS; kt++) {
        const int cur = kt % STAGES;
        asm volatile("cp.async.wait_group 2;\n" ::);
        __syncthreads();

#pragma unroll
        for (int ks = 0; ks < 8; ks++) {
            const int sub = ks >> 2;
            const int ck  = ks & 3;
            uint32_t af[2][4], bf[4][4];
#pragma unroll
            for (int mt = 0; mt < 2; mt++) {
                int r  = wm * 32 + mt * 16 + lr;
                int ch = (ck * 2 + hf) ^ (r & 7);
                LDSM_X4(af[mt], sA + cur * ASTAGE + sub * SUBTILE + r * 128 + (ch << 4));
            }
#pragma unroll
            for (int p = 0; p < 4; p++) {
                int r  = wn * 64 + p * 16 + lr;
                int ch = (ck * 2 + hf) ^ (r & 7);
                LDSM_X4(bf[p], sB + cur * BSTAGE + sub * SUBTILE + r * 128 + (ch << 4));
            }
#pragma unroll
            for (int mt = 0; mt < 2; mt++)
#pragma unroll
                for (int p = 0; p < 4; p++)
#pragma unroll
                    for (int q = 0; q < 2; q++)
                        MMA16816(acc[mt][p * 2 + q], af[mt], bf[p][q], bf[p][q + 2]);
        }
        __syncthreads();

        if (kt + STAGES < ITERS)
            load_tiles(Ag, Bg, kt + STAGES, tid, sA, sB);
        else
            asm volatile("cp.async.commit_group;\n" ::);
    }

    // epilogue -> split-K partial buffer
    float* P = g_P + (size_t)z * BATCH * NOUT;
#pragma unroll
    for (int mt = 0; mt < 2; mt++)
#pragma unroll
        for (int nt = 0; nt < 8; nt++) {
            int row0 = m0 + wm * 32 + mt * 16 + (lane >> 2);
            int col  = n0 + wn * 64 + nt * 8 + (lane & 3) * 2;
            *(float2*)&P[(size_t)row0 * NOUT + col] =
                make_float2(acc[mt][nt][0], acc[mt][nt][1]);
            *(float2*)&P[(size_t)(row0 + 8) * NOUT + col] =
                make_float2(acc[mt][nt][2], acc[mt][nt][3]);
        }
}

// ---------------------------------------------------------------------------
// Deterministic fixed-order split-K reduction (vectorized)
// ---------------------------------------------------------------------------
__global__ void __launch_bounds__(256) reduce_kernel(float* __restrict__ Out) {
    int idx = blockIdx.x * 256 + threadIdx.x;           // over float4s
    const float4* P0 = (const float4*)(g_P + 0 * (size_t)BATCH * NOUT);
    const float4* P1 = (const float4*)(g_P + 1 * (size_t)BATCH * NOUT);
    const float4* P2 = (const float4*)(g_P + 2 * (size_t)BATCH * NOUT);
    const float4* P3 = (const float4*)(g_P + 3 * (size_t)BATCH * NOUT);
    float4 a = P0[idx], b = P1[idx], c = P2[idx], d = P3[idx];
    float4 r;
    r.x = (a.x + b.x) + (c.x + d.x);
    r.y = (a.y + b.y) + (c.y + d.y);
    r.z = (a.z + b.z) + (c.z + d.z);
    r.w = (a.w + b.w) + (c.w + d.w);
    ((float4*)Out)[idx] = r;
}

// ---------------------------------------------------------------------------
extern "C" void kernel_launch(void* const* d_in, const int* in_sizes, int n_in,
                              void* d_out, int out_size) {
    const float* X = nullptr;
    const float* C = nullptr;
    const float* W = nullptr;
    for (int i = 0; i < n_in; i++) {
        if      (in_sizes[i] == BATCH * NIN)      X = (const float*)d_in[i];
        else if (in_sizes[i] == NIN * NOUT * NB)  C = (const float*)d_in[i];
        else if (in_sizes[i] == NIN * NOUT)       W = (const float*)d_in[i];
    }

    static bool attr_done = false;
    if (!attr_done) {
        cudaFuncSetAttribute(kan_gemm_kernel,
                             cudaFuncAttributeMaxDynamicSharedMemorySize, SMEM_TOTAL);
        attr_done = true;
    }

    prep_a_kernel<<<(BATCH * NIN / 2) / 256, 256>>>(X);
    prep_b_kernel<<<(NIN * NOUT / 2) / 256, 256>>>(W, C);

    dim3 grid(BATCH / BM, NOUT / BN, SPLITK);   // (8, 4, 4) = 128 CTAs
    kan_gemm_kernel<<<grid, 256, SMEM_TOTAL>>>();

    reduce_kernel<<<(BATCH * NOUT / 4) / 256, 256>>>((float*)d_out);
}